// round 1
// baseline (speedup 1.0000x reference)
#include <cuda_runtime.h>
#include <math.h>

// NUFFTLayerMultiChannelOneSided: analytic band-limited reformulation.
//
// Key identities (L = 1, N = 2001, tau = 12/(2*pi*N)^2, sigma = sigma_var[0]):
//   fft_g[b, m] = N * exp(-2*pi^2*m^2*sigma^2) * (A_b[m] - i*B_b[m]),
//     A_b[m] = sum_p cos(2*pi*m*x_p),  B_b[m] = sum_p sin(2*pi*m*x_p)
//   (aliasing terms ~ e^{-7900} -> exactly 0 in fp32; modes |m| > ~105
//    underflow fp32 in the reference as well, so M = 128 modes suffice)
//   irfft[b,c,n] = sum_m mult_c[m]*exp(-2*pi^2*m^2*s^2)*(A cos(2pi m n/N) + B sin(2pi m n/N))
//   fmm[b,p,c]   = (1/N) * sum_{|j|<=8, 0<=m0+j<=2000} exp(-(x_p - X_m)^2/(4 tau)) * irfft[b,c,m]
//     (window decays below 1e-11 past 6 grid steps; reference does NOT wrap it -> clamp)

#define NMESHC 2001
#define MMAX   128
#define NMODES (MMAX + 1)
#define NBATCH 8
#define NPART  1024

__device__ float g_A[NBATCH][NMODES];
__device__ float g_B[NBATCH][NMODES];
__device__ float g_f[NBATCH][2][NMESHC];

// ---------------------------------------------------------------------------
// K1: per-mode cos/sin particle sums.  One block per (mode m, batch b).
// Phase m*x computed exactly in double (31-bit product), reduced to [-0.5,0.5],
// so __sincosf runs in its max-accuracy range.
// ---------------------------------------------------------------------------
__global__ __launch_bounds__(256) void k_modes(const float* __restrict__ x)
{
    const int m = blockIdx.x;          // 0..128
    const int b = blockIdx.y;          // 0..7
    const int t = threadIdx.x;         // 0..255
    const float* xb = x + b * NPART;

    const double dm = (double)m;
    float sa = 0.f, sb = 0.f;
#pragma unroll
    for (int i = 0; i < 4; ++i) {
        float  xv = xb[t + 256 * i];
        double tt = dm * (double)xv;               // exact in double
        float  r  = (float)(tt - rint(tt));        // in [-0.5, 0.5]
        float  sn, cs;
        __sincosf(6.28318530717958647692f * r, &sn, &cs);
        sa += cs;
        sb += sn;
    }

    __shared__ float shA[8], shB[8];
#pragma unroll
    for (int o = 16; o > 0; o >>= 1) {
        sa += __shfl_down_sync(0xffffffffu, sa, o);
        sb += __shfl_down_sync(0xffffffffu, sb, o);
    }
    if ((t & 31) == 0) { shA[t >> 5] = sa; shB[t >> 5] = sb; }
    __syncthreads();
    if (t < 32) {
        sa = (t < 8) ? shA[t] : 0.f;
        sb = (t < 8) ? shB[t] : 0.f;
#pragma unroll
        for (int o = 4; o > 0; o >>= 1) {
            sa += __shfl_down_sync(0xffffffffu, sa, o);
            sb += __shfl_down_sync(0xffffffffu, sb, o);
        }
        if (t == 0) { g_A[b][m] = sa; g_B[b][m] = sb; }
    }
}

// ---------------------------------------------------------------------------
// K2: physical-space field at all 2001 grid points, both channels.
// Thread n iterates modes with a complex rotation recurrence (pure FMA).
// Spectral multipliers (incl. the +-m fold factor 2) are staged in smem.
// ---------------------------------------------------------------------------
__global__ __launch_bounds__(128) void k_field(
    const float* __restrict__ sigma_var,
    const float* __restrict__ shift0,
    const float* __restrict__ shift1,
    const float* __restrict__ amp0,
    const float* __restrict__ amp1)
{
    const int b = blockIdx.y;
    const int t = threadIdx.x;
    const int n = blockIdx.x * 128 + t;

    __shared__ float sA[NMODES], sB[NMODES], sV0[NMODES], sV1[NMODES];

    const double TWO_PI_D = 6.283185307179586476925286766559;
    const double twoPiN   = TWO_PI_D * 2001.0;
    const double taud     = 12.0 / (twoPiN * twoPiN);
    const float  TAUF     = (float)taud;
    const float  SQPIOTAU = (float)sqrt(3.14159265358979323846 / taud);

    const float s    = sigma_var[0];
    const float q0   = 25.f * shift0[0] * shift0[0];
    const float q1   = 25.f * shift1[0] * shift1[0];
    const float a0   = amp0[0];
    const float a1   = amp1[0];
    const float FOURPI = 12.566370614359172f;
    const float coef = TAUF - 0.5f * s * s;   // exp(K^2*tau) * exp(-K^2*s^2/2)

    for (int m = t; m < NMODES; m += 128) {
        sA[m] = g_A[b][m];
        sB[m] = g_B[b][m];
        float fm = (float)m;
        float kk = 6.2831853071795865f * fm;
        float K2 = kk * kk;
        float e  = SQPIOTAU * expf(coef * K2);      // underflows to 0 for large m (as ref)
        float fold = (m == 0) ? 1.f : 2.f;
        sV0[m] = fold * (-a0) * FOURPI / (K2 + q0) * e;
        float inv = 1.f / (K2 + q1);
        sV1[m] = fold * a1 * FOURPI * inv * inv * e;
    }
    __syncthreads();
    if (n >= NMESHC) return;

    // rotation step e^{i*2*pi*n/N}, computed once in double for accuracy
    double ang, sd, cd;
    ang = TWO_PI_D * ((double)n / 2001.0);
    sincos(ang, &sd, &cd);
    const float cr = (float)cd, sr = (float)sd;

    float zr = 1.f, zi = 0.f;                 // e^{i*2*pi*m*n/N}, m = 0
    float acc0 = sV0[0] * sA[0];
    float acc1 = sV1[0] * sA[0];
#pragma unroll 4
    for (int m = 1; m < NMODES; ++m) {
        float nzr = fmaf(zr, cr, -zi * sr);
        float nzi = fmaf(zi, cr,  zr * sr);
        zr = nzr; zi = nzi;
        float tt = fmaf(sA[m], zr, sB[m] * zi);
        acc0 = fmaf(sV0[m], tt, acc0);
        acc1 = fmaf(sV1[m], tt, acc1);
    }
    g_f[b][0][n] = acc0;
    g_f[b][1][n] = acc1;
}

// ---------------------------------------------------------------------------
// K3: resample the field at particle positions with the (narrow) gaussian
// gridding window.  17 taps, clamped to [0, 2000] (reference does not wrap).
// ---------------------------------------------------------------------------
__global__ __launch_bounds__(256) void k_resample(const float* __restrict__ x,
                                                  float* __restrict__ out)
{
    const int gid = blockIdx.x * 256 + threadIdx.x;   // 0..8191
    const int b   = gid >> 10;
    const float xv = x[gid];

    const double TWO_PI_D = 6.283185307179586476925286766559;
    const double twoPiN   = TWO_PI_D * 2001.0;
    const float  TAUF     = (float)(12.0 / (twoPiN * twoPiN));
    const float  inv4tau  = 1.f / (4.f * TAUF);

    const int m0 = __float2int_rn(xv * 2001.0f);
    float acc0 = 0.f, acc1 = 0.f;
#pragma unroll
    for (int j = -8; j <= 8; ++j) {
        int m = m0 + j;
        if (m < 0 || m > 2000) continue;
        float X = (float)((double)m * (1.0 / 2001.0));  // matches fp32(linspace)
        float d = xv - X;
        float w = __expf(-d * d * inv4tau);
        acc0 = fmaf(w, g_f[b][0][m], acc0);
        acc1 = fmaf(w, g_f[b][1][m], acc1);
    }
    const float invN = (float)(1.0 / 2001.0);
    out[2 * gid]     = acc0 * invN;
    out[2 * gid + 1] = acc1 * invN;
}

// ---------------------------------------------------------------------------
extern "C" void kernel_launch(void* const* d_in, const int* in_sizes, int n_in,
                              void* d_out, int out_size)
{
    (void)in_sizes; (void)n_in; (void)out_size;
    const float* x         = (const float*)d_in[0];
    const float* sigma_var = (const float*)d_in[1];
    const float* shift0    = (const float*)d_in[2];
    const float* shift1    = (const float*)d_in[3];
    const float* amp0      = (const float*)d_in[4];
    const float* amp1      = (const float*)d_in[5];
    float* out = (float*)d_out;

    k_modes   <<<dim3(NMODES, NBATCH), 256>>>(x);
    k_field   <<<dim3(16,     NBATCH), 128>>>(sigma_var, shift0, shift1, amp0, amp1);
    k_resample<<<32, 256>>>(x, out);
}